// round 1
// baseline (speedup 1.0000x reference)
#include <cuda_runtime.h>
#include <cstdint>
#include <math.h>

#define AST 332   // activation smem row stride (u32), 332%32=12 -> conflict-free A frags
#define WST 264   // weight tile row stride (u32), 264%32=8 -> conflict-free B frags

// Padded tf32 weights: w00[64x256] w01..w03[256x256] w10[320x256] w11..w13[256x256] cw0[288x128]
__device__ uint32_t g_w[528384];

#define OFF_W00 0
#define OFF_W01 16384
#define OFF_W02 81920
#define OFF_W03 147456
#define OFF_W10 212992
#define OFF_W11 294912
#define OFF_W12 360448
#define OFF_W13 425984
#define OFF_CW0 491520

__device__ __forceinline__ uint32_t f2tf32(float f){
  uint32_t u; asm("cvt.rna.tf32.f32 %0, %1;" : "=r"(u) : "f"(f)); return u;
}

__device__ __forceinline__ void mma_tf32(float* c, const uint32_t* a, uint32_t b0, uint32_t b1){
  asm volatile("mma.sync.aligned.m16n8k8.row.col.f32.tf32.tf32.f32 "
    "{%0,%1,%2,%3},{%4,%5,%6,%7},{%8,%9},{%0,%1,%2,%3};\n"
    : "+f"(c[0]),"+f"(c[1]),"+f"(c[2]),"+f"(c[3])
    : "r"(a[0]),"r"(a[1]),"r"(a[2]),"r"(a[3]),"r"(b0),"r"(b1));
}

// Convert + zero-pad one weight matrix into g_w (row-major [Kpad][N], rows >= Kreal zeroed)
__global__ void prep_kernel(const float* __restrict__ src, int Kreal, int Kpad, int N, int off){
  int idx = blockIdx.x * blockDim.x + threadIdx.x;
  if (idx >= Kpad * N) return;
  int k = idx / N, n = idx - k * N;
  float v = (k < Kreal) ? src[k * N + n] : 0.0f;
  g_w[off + idx] = f2tf32(v);
}

template<int NCOLS>
__device__ __forceinline__ void issue_tile(const uint32_t* __restrict__ Wg, uint32_t* wbuf,
                                           int s, int S, int tid){
  if (s < S){
    const uint32_t* src = Wg + s * (8 * NCOLS);
    uint32_t* dst = wbuf + (s & 3) * (8 * WST);
    #pragma unroll
    for (int c = 0; c < (8 * NCOLS) / 4; c += 256){
      int cc  = c + tid;
      int row = cc / (NCOLS / 4);
      int col = (cc % (NCOLS / 4)) * 4;
      unsigned sa = (unsigned)__cvta_generic_to_shared(dst + row * WST + col);
      asm volatile("cp.async.cg.shared.global [%0], [%1], 16;\n"
                   :: "r"(sa), "l"(src + row * NCOLS + col));
    }
  }
  asm volatile("cp.async.commit_group;\n" ::: "memory");
}

// One dense layer: act[:, 0:KPAD] (tf32) @ W[KPAD x NCOLS] + bias -> act[:, 0:NCOLS] (tf32)
template<int KPAD, int NCOLS, bool RELU>
__device__ void mlp_layer(uint32_t* act, uint32_t* wbuf,
                          const uint32_t* __restrict__ Wg,
                          const float* __restrict__ bias, int tid)
{
  constexpr int S  = KPAD / 8;
  constexpr int NT = NCOLS / 16;   // 8-wide n-tiles per warp (2 warp-cols)
  const int wid = tid >> 5, lane = tid & 31;
  const int gq = lane >> 2, gt = lane & 3;
  const int mbase = (wid & 3) * 32;
  const int nbase = (wid >> 2) * (NCOLS / 2);

  float acc[2][NT][4];
  #pragma unroll
  for (int mt = 0; mt < 2; mt++)
    #pragma unroll
    for (int nt = 0; nt < NT; nt++)
      #pragma unroll
      for (int j = 0; j < 4; j++) acc[mt][nt][j] = 0.0f;

  issue_tile<NCOLS>(Wg, wbuf, 0, S, tid);
  issue_tile<NCOLS>(Wg, wbuf, 1, S, tid);
  issue_tile<NCOLS>(Wg, wbuf, 2, S, tid);

  for (int s = 0; s < S; s++){
    asm volatile("cp.async.wait_group 2;\n" ::: "memory");
    __syncthreads();
    issue_tile<NCOLS>(Wg, wbuf, s + 3, S, tid);

    const uint32_t* wb = wbuf + (s & 3) * (8 * WST);
    const int k0 = s * 8;
    uint32_t a[2][4];
    #pragma unroll
    for (int mt = 0; mt < 2; mt++){
      int base = (mbase + mt * 16 + gq) * AST + k0 + gt;
      a[mt][0] = act[base];
      a[mt][1] = act[base + 8 * AST];
      a[mt][2] = act[base + 4];
      a[mt][3] = act[base + 8 * AST + 4];
    }
    #pragma unroll
    for (int nt = 0; nt < NT; nt++){
      int c0 = nbase + nt * 8 + gq;
      uint32_t b0 = wb[gt * WST + c0];
      uint32_t b1 = wb[(gt + 4) * WST + c0];
      mma_tf32(acc[0][nt], a[0], b0, b1);
      mma_tf32(acc[1][nt], a[1], b0, b1);
    }
  }
  __syncthreads();   // all A reads done before overwriting act

  #pragma unroll
  for (int mt = 0; mt < 2; mt++)
    #pragma unroll
    for (int nt = 0; nt < NT; nt++)
      #pragma unroll
      for (int j = 0; j < 4; j++){
        int row = mbase + mt * 16 + gq + ((j & 2) << 2);
        int col = nbase + nt * 8 + gt * 2 + (j & 1);
        float v = acc[mt][nt][j] + __ldg(bias + col);
        if (RELU) v = fmaxf(v, 0.0f);
        act[row * AST + col] = f2tf32(v);
      }
  __syncthreads();
}

__global__ void __launch_bounds__(256, 1)
nerf_kernel(const float* __restrict__ pos, const float* __restrict__ dir,
            const float* __restrict__ b00, const float* __restrict__ b01,
            const float* __restrict__ b02, const float* __restrict__ b03,
            const float* __restrict__ b10, const float* __restrict__ b11,
            const float* __restrict__ b12, const float* __restrict__ b13,
            const float* __restrict__ cb0, const float* __restrict__ cw1,
            const float* __restrict__ cb1,
            float* __restrict__ out, int nrays)
{
  extern __shared__ uint32_t smem_u32[];
  uint32_t* act  = smem_u32;                   // 128 * 332
  uint32_t* wbuf = act + 128 * AST;            // 4 * 8 * 264
  uint32_t* deb  = wbuf + 4 * 8 * WST;         // 128 * 28

  const int tid = threadIdx.x;

  // ---- Positional / directional encoding (fp32 math, stored as tf32) ----
  if (tid < 128){
    const int r = tid;
    const int g = blockIdx.x * 128 + r;
    uint32_t* row = act + r * AST;
    #pragma unroll
    for (int d = 0; d < 3; d++){
      float p = pos[g * 3 + d];
      uint32_t up = f2tf32(p);
      row[d] = up; row[256 + d] = up;
      float f = 1.0f;
      #pragma unroll
      for (int l = 0; l < 10; l++){
        float sv, cv; sincosf(p * f, &sv, &cv);
        uint32_t us = f2tf32(sv), uc = f2tf32(cv);
        row[3  + d * 10 + l] = us; row[256 + 3  + d * 10 + l] = us;
        row[33 + d * 10 + l] = uc; row[256 + 33 + d * 10 + l] = uc;
        f *= 2.0f;
      }
    }
    row[63] = 0u; row[319] = 0u;        // K-padding slots must be finite
    uint32_t* dr = deb + r * 28;
    #pragma unroll
    for (int d = 0; d < 3; d++){
      float p = dir[g * 3 + d];
      dr[d] = f2tf32(p);
      float f = 1.0f;
      #pragma unroll
      for (int l = 0; l < 4; l++){
        float sv, cv; sincosf(p * f, &sv, &cv);
        dr[3  + d * 4 + l] = f2tf32(sv);
        dr[15 + d * 4 + l] = f2tf32(cv);
        f *= 2.0f;
      }
    }
  }
  __syncthreads();

  // ---- MLP trunk ----
  mlp_layer< 64, 256, true >(act, wbuf, g_w + OFF_W00, b00, tid);
  mlp_layer<256, 256, true >(act, wbuf, g_w + OFF_W01, b01, tid);
  mlp_layer<256, 256, true >(act, wbuf, g_w + OFF_W02, b02, tid);
  mlp_layer<256, 256, true >(act, wbuf, g_w + OFF_W03, b03, tid);
  mlp_layer<320, 256, true >(act, wbuf, g_w + OFF_W10, b10, tid);  // [z, pe]
  mlp_layer<256, 256, true >(act, wbuf, g_w + OFF_W11, b11, tid);
  mlp_layer<256, 256, true >(act, wbuf, g_w + OFF_W12, b12, tid);
  mlp_layer<256, 256, false>(act, wbuf, g_w + OFF_W13, b13, tid);  // linear

  // swap pe -> de in the concat region [256..288)
  if (tid < 128){
    uint32_t* row = act + tid * AST + 256;
    const uint32_t* dr = deb + tid * 28;
    #pragma unroll
    for (int j = 0; j < 27; j++) row[j] = dr[j];
    #pragma unroll
    for (int j = 27; j < 32; j++) row[j] = 0u;
  }
  __syncthreads();

  mlp_layer<288, 128, true>(act, wbuf, g_w + OFF_CW0, cb0, tid);   // [z, de] -> h

  // ---- tiny head (128 -> 4) + activations, fp32 scalar ----
  if (tid < 128){
    const int r = tid;
    const int g = blockIdx.x * 128 + r;
    float o0 = cb1[0], o1 = cb1[1], o2 = cb1[2], o3 = cb1[3];
    const uint32_t* row = act + r * AST;
    #pragma unroll 4
    for (int k = 0; k < 128; k++){
      float h = __uint_as_float(row[k]);
      float4 w = *reinterpret_cast<const float4*>(cw1 + k * 4);
      o0 += h * w.x; o1 += h * w.y; o2 += h * w.z; o3 += h * w.w;
    }
    float d  = o3;
    float sp = fmaxf(d, 0.0f) + log1pf(expf(-fabsf(d)));   // stable softplus
    out[g] = (d > 8.0f) ? d : sp;
    out[nrays + g * 3 + 0] = 1.0f / (1.0f + expf(-o0));
    out[nrays + g * 3 + 1] = 1.0f / (1.0f + expf(-o1));
    out[nrays + g * 3 + 2] = 1.0f / (1.0f + expf(-o2));
  }
}

#define SMEM_BYTES ((128 * AST + 4 * 8 * WST + 128 * 28) * 4)

extern "C" void kernel_launch(void* const* d_in, const int* in_sizes, int n_in,
                              void* d_out, int out_size)
{
  const float* pos = (const float*)d_in[0];
  const float* dir = (const float*)d_in[1];
  // d_in[2..4] = pixel_width, t_start, t_end (unused by reference)
  const float* w00 = (const float*)d_in[5];  const float* b00 = (const float*)d_in[6];
  const float* w01 = (const float*)d_in[7];  const float* b01 = (const float*)d_in[8];
  const float* w02 = (const float*)d_in[9];  const float* b02 = (const float*)d_in[10];
  const float* w03 = (const float*)d_in[11]; const float* b03 = (const float*)d_in[12];
  const float* w10 = (const float*)d_in[13]; const float* b10 = (const float*)d_in[14];
  const float* w11 = (const float*)d_in[15]; const float* b11 = (const float*)d_in[16];
  const float* w12 = (const float*)d_in[17]; const float* b12 = (const float*)d_in[18];
  const float* w13 = (const float*)d_in[19]; const float* b13 = (const float*)d_in[20];
  const float* cw0 = (const float*)d_in[21]; const float* cb0 = (const float*)d_in[22];
  const float* cw1 = (const float*)d_in[23]; const float* cb1 = (const float*)d_in[24];
  float* out = (float*)d_out;

  const int nrays = in_sizes[0] / 3;

  cudaFuncSetAttribute(nerf_kernel, cudaFuncAttributeMaxDynamicSharedMemorySize, SMEM_BYTES);

  // weight conversion / padding to tf32 (cheap; runs inside the graph each replay)
  prep_kernel<<<( 64 * 256 + 255) / 256, 256>>>(w00,  63,  64, 256, OFF_W00);
  prep_kernel<<<(256 * 256 + 255) / 256, 256>>>(w01, 256, 256, 256, OFF_W01);
  prep_kernel<<<(256 * 256 + 255) / 256, 256>>>(w02, 256, 256, 256, OFF_W02);
  prep_kernel<<<(256 * 256 + 255) / 256, 256>>>(w03, 256, 256, 256, OFF_W03);
  prep_kernel<<<(320 * 256 + 255) / 256, 256>>>(w10, 319, 320, 256, OFF_W10);
  prep_kernel<<<(256 * 256 + 255) / 256, 256>>>(w11, 256, 256, 256, OFF_W11);
  prep_kernel<<<(256 * 256 + 255) / 256, 256>>>(w12, 256, 256, 256, OFF_W12);
  prep_kernel<<<(256 * 256 + 255) / 256, 256>>>(w13, 256, 256, 256, OFF_W13);
  prep_kernel<<<(288 * 128 + 255) / 256, 256>>>(cw0, 283, 288, 128, OFF_CW0);

  nerf_kernel<<<nrays / 128, 256, SMEM_BYTES>>>(
      pos, dir, b00, b01, b02, b03, b10, b11, b12, b13, cb0, cw1, cb1, out, nrays);
}

// round 3
// speedup vs baseline: 1.8589x; 1.8589x over previous
#include <cuda_runtime.h>
#include <cuda_fp16.h>
#include <cstdint>
#include <math.h>

#define AST 164   // activation smem row stride in u32 (half2 pairs); 164%32=4 -> conflict-free A frags
#define WST 264   // weight tile row stride in u32; 264%32=8 -> conflict-free B frags

// Packed fp16 weights, pre-tiled: chunk layout [S][8][N] u32, element (s,kk,n) = half2(W[16s+2kk][n], W[16s+2kk+1][n])
__device__ uint32_t g_w[264192];

#define OFF_W00 0
#define OFF_W01 8192
#define OFF_W02 40960
#define OFF_W03 73728
#define OFF_W10 106496
#define OFF_W11 147456
#define OFF_W12 180224
#define OFF_W13 212992
#define OFF_CW0 245760
#define W_TOTAL 264192

__device__ __forceinline__ void mma_f16(float* c, const uint32_t* a, uint32_t b0, uint32_t b1){
  asm volatile("mma.sync.aligned.m16n8k16.row.col.f32.f16.f16.f32 "
    "{%0,%1,%2,%3},{%4,%5,%6,%7},{%8,%9},{%0,%1,%2,%3};\n"
    : "+f"(c[0]),"+f"(c[1]),"+f"(c[2]),"+f"(c[3])
    : "r"(a[0]),"r"(a[1]),"r"(a[2]),"r"(a[3]),"r"(b0),"r"(b1));
}

// Single fused prep: convert all 9 weight matrices to fp16, zero-pad K, pack half2 pairs
// along K, tiled as [S][8][N] u32 chunks (contiguous 8KB per K16-stage).
__global__ void prep_all(const float* __restrict__ w00, const float* __restrict__ w01,
                         const float* __restrict__ w02, const float* __restrict__ w03,
                         const float* __restrict__ w10, const float* __restrict__ w11,
                         const float* __restrict__ w12, const float* __restrict__ w13,
                         const float* __restrict__ cw0)
{
  int i = blockIdx.x * blockDim.x + threadIdx.x;
  if (i >= W_TOTAL) return;
  const float* src; int Kreal, N, off;
  if      (i < OFF_W01){ src=w00; Kreal= 63; N=256; off=OFF_W00; }
  else if (i < OFF_W02){ src=w01; Kreal=256; N=256; off=OFF_W01; }
  else if (i < OFF_W03){ src=w02; Kreal=256; N=256; off=OFF_W02; }
  else if (i < OFF_W10){ src=w03; Kreal=256; N=256; off=OFF_W03; }
  else if (i < OFF_W11){ src=w10; Kreal=319; N=256; off=OFF_W10; }
  else if (i < OFF_W12){ src=w11; Kreal=256; N=256; off=OFF_W11; }
  else if (i < OFF_W13){ src=w12; Kreal=256; N=256; off=OFF_W12; }
  else if (i < OFF_CW0){ src=w13; Kreal=256; N=256; off=OFF_W13; }
  else                 { src=cw0; Kreal=283; N=128; off=OFF_CW0; }
  int local = i - off;
  int n  = local % N;
  int kk = (local / N) & 7;
  int s  = local / (8 * N);
  int k0 = s * 16 + kk * 2;
  float v0 = (k0     < Kreal) ? src[ k0      * N + n] : 0.0f;
  float v1 = (k0 + 1 < Kreal) ? src[(k0 + 1) * N + n] : 0.0f;
  __half2 h = __floats2half2_rn(v0, v1);
  g_w[i] = *reinterpret_cast<uint32_t*>(&h);
}

template<int NCOLS>   // NCOLS = N = u32 entries per chunk row
__device__ __forceinline__ void issue_tile(const uint32_t* __restrict__ Wg, uint32_t* wbuf,
                                           int s, int S, int tid){
  if (s < S){
    const uint32_t* src = Wg + s * (8 * NCOLS);
    uint32_t* dst = wbuf + (s & 3) * (8 * WST);
    #pragma unroll
    for (int c = tid; c < (8 * NCOLS) / 4; c += 256){
      int row = c / (NCOLS / 4);
      int col = (c % (NCOLS / 4)) * 4;
      unsigned sa = (unsigned)__cvta_generic_to_shared(dst + row * WST + col);
      asm volatile("cp.async.cg.shared.global [%0], [%1], 16;\n"
                   :: "r"(sa), "l"(src + row * NCOLS + col));
    }
  }
  asm volatile("cp.async.commit_group;\n" ::: "memory");
}

// One dense layer: act[:, 0:KH halves] (fp16) @ W[KH x NCOLS] + bias -> act[:, 0:NCOLS halves]
// Warp tiling: 2 m-groups x 4 n-groups, 64x64 per warp (mt=4, NT=NCOLS/32).
template<int KH, int NCOLS, bool RELU>
__device__ void mlp_layer(uint32_t* act, uint32_t* wbuf,
                          const uint32_t* __restrict__ Wg,
                          const float* __restrict__ bias, int tid)
{
  constexpr int S  = KH / 16;
  constexpr int NT = NCOLS / 32;
  const int wid = tid >> 5, lane = tid & 31;
  const int gq = lane >> 2, gt = lane & 3;
  const int mbase = (wid & 1) * 64;
  const int nbase = (wid >> 1) * (NCOLS / 4);   // in halves

  float acc[4][NT][4];
  #pragma unroll
  for (int mt = 0; mt < 4; mt++)
    #pragma unroll
    for (int nt = 0; nt < NT; nt++)
      #pragma unroll
      for (int j = 0; j < 4; j++) acc[mt][nt][j] = 0.0f;

  issue_tile<NCOLS>(Wg, wbuf, 0, S, tid);
  issue_tile<NCOLS>(Wg, wbuf, 1, S, tid);
  issue_tile<NCOLS>(Wg, wbuf, 2, S, tid);

  for (int s = 0; s < S; s++){
    asm volatile("cp.async.wait_group 2;\n" ::: "memory");
    __syncthreads();
    issue_tile<NCOLS>(Wg, wbuf, s + 3, S, tid);

    const uint32_t* wb = wbuf + (s & 3) * (8 * WST);
    const int k0 = s * 8;   // u32 col
    uint32_t a[4][4];
    #pragma unroll
    for (int mt = 0; mt < 4; mt++){
      int base = (mbase + mt * 16 + gq) * AST + k0 + gt;
      a[mt][0] = act[base];
      a[mt][1] = act[base + 8 * AST];
      a[mt][2] = act[base + 4];
      a[mt][3] = act[base + 8 * AST + 4];
    }
    #pragma unroll
    for (int nt = 0; nt < NT; nt++){
      int c0 = nbase / 2 * 2;  // keep nbase semantics clear; n index below
      int n  = (nbase / 2) + nt * 8 + gq;       // n in u32 units == neuron index? no:
      (void)c0;
      // chunk rows hold one u32 per neuron n: n index = nbase_neuron + nt*8 + gq
      int nn = (nbase >> 0) / 1;                // nbase is in halves == neuron count? see below
      (void)nn; (void)n;
      int cn = (nbase) / 1;                     // neurons: nbase halves == neurons since 1 col per neuron
      cn = (nbase);                             // NCOLS/4 neurons per warp group
      int col = (cn >> 0);
      col = nbase + 0;                          // final: neuron base
      int nidx = (nbase) + nt * 8 + gq;
      (void)col;
      uint32_t b0 = wb[gt * WST + nidx];
      uint32_t b1 = wb[(gt + 4) * WST + nidx];
      mma_f16(acc[0][nt], a[0], b0, b1);
      mma_f16(acc[1][nt], a[1], b0, b1);
      mma_f16(acc[2][nt], a[2], b0, b1);
      mma_f16(acc[3][nt], a[3], b0, b1);
    }
  }
  __syncthreads();   // all A reads done before overwriting act

  #pragma unroll
  for (int mt = 0; mt < 4; mt++)
    #pragma unroll
    for (int nt = 0; nt < NT; nt++){
      int col = nbase + nt * 8 + 2 * gt;                  // halves (even)
      int ucol = (nbase + nt * 8) / 2 + gt;               // u32 col
      float2 bb = *reinterpret_cast<const float2*>(bias + col);
      float v0 = acc[mt][nt][0] + bb.x;
      float v1 = acc[mt][nt][1] + bb.y;
      float v2 = acc[mt][nt][2] + bb.x;
      float v3 = acc[mt][nt][3] + bb.y;
      if (RELU){
        v0 = fmaxf(v0, 0.0f); v1 = fmaxf(v1, 0.0f);
        v2 = fmaxf(v2, 0.0f); v3 = fmaxf(v3, 0.0f);
      }
      __half2 h01 = __floats2half2_rn(v0, v1);
      __half2 h23 = __floats2half2_rn(v2, v3);
      int row = mbase + mt * 16 + gq;
      act[row * AST + ucol]       = *reinterpret_cast<uint32_t*>(&h01);
      act[(row + 8) * AST + ucol] = *reinterpret_cast<uint32_t*>(&h23);
    }
  __syncthreads();
}

__global__ void __launch_bounds__(256, 1)
nerf_kernel(const float* __restrict__ pos, const float* __restrict__ dir,
            const float* __restrict__ b00, const float* __restrict__ b01,
            const float* __restrict__ b02, const float* __restrict__ b03,
            const float* __restrict__ b10, const float* __restrict__ b11,
            const float* __restrict__ b12, const float* __restrict__ b13,
            const float* __restrict__ cb0, const float* __restrict__ cw1,
            const float* __restrict__ cb1,
            float* __restrict__ out, int nrays)
{
  extern __shared__ uint32_t smem_u32[];
  uint32_t* act  = smem_u32;                   // 128 * 164
  uint32_t* wbuf = act + 128 * AST;            // 4 * 8 * 264
  uint32_t* deb  = wbuf + 4 * 8 * WST;         // 128 * 14

  const int tid = threadIdx.x;

  // ---- Positional / directional encoding (fp32 math, packed fp16) ----
  if (tid < 128){
    const int r = tid;
    const int g = blockIdx.x * 128 + r;
    float pe[64];
    pe[63] = 0.0f;
    #pragma unroll
    for (int d = 0; d < 3; d++){
      float p = pos[g * 3 + d];
      pe[d] = p;
      float f = 1.0f;
      #pragma unroll
      for (int l = 0; l < 10; l++){
        float sv, cv; sincosf(p * f, &sv, &cv);
        pe[3  + d * 10 + l] = sv;
        pe[33 + d * 10 + l] = cv;
        f *= 2.0f;
      }
    }
    uint32_t* row = act + r * AST;
    #pragma unroll
    for (int j = 0; j < 32; j++){
      __half2 h = __floats2half2_rn(pe[2*j], pe[2*j+1]);
      uint32_t u = *reinterpret_cast<uint32_t*>(&h);
      row[j] = u; row[128 + j] = u;            // copy for [z, pe] concat
    }
    float de[28];
    de[27] = 0.0f;
    #pragma unroll
    for (int d = 0; d < 3; d++){
      float p = dir[g * 3 + d];
      de[d] = p;
      float f = 1.0f;
      #pragma unroll
      for (int l = 0; l < 4; l++){
        float sv, cv; sincosf(p * f, &sv, &cv);
        de[3  + d * 4 + l] = sv;
        de[15 + d * 4 + l] = cv;
        f *= 2.0f;
      }
    }
    uint32_t* dr = deb + r * 14;
    #pragma unroll
    for (int j = 0; j < 14; j++){
      __half2 h = __floats2half2_rn(de[2*j], de[2*j+1]);
      dr[j] = *reinterpret_cast<uint32_t*>(&h);
    }
  }
  __syncthreads();

  // ---- MLP trunk ----
  mlp_layer< 64, 256, true >(act, wbuf, g_w + OFF_W00, b00, tid);
  mlp_layer<256, 256, true >(act, wbuf, g_w + OFF_W01, b01, tid);
  mlp_layer<256, 256, true >(act, wbuf, g_w + OFF_W02, b02, tid);
  mlp_layer<256, 256, true >(act, wbuf, g_w + OFF_W03, b03, tid);
  mlp_layer<320, 256, true >(act, wbuf, g_w + OFF_W10, b10, tid);  // [z, pe]
  mlp_layer<256, 256, true >(act, wbuf, g_w + OFF_W11, b11, tid);
  mlp_layer<256, 256, true >(act, wbuf, g_w + OFF_W12, b12, tid);
  mlp_layer<256, 256, false>(act, wbuf, g_w + OFF_W13, b13, tid);  // linear

  // swap pe -> de in the concat region: u32 cols [128..144)
  if (tid < 128){
    uint32_t* row = act + tid * AST + 128;
    const uint32_t* dr = deb + tid * 14;
    #pragma unroll
    for (int j = 0; j < 14; j++) row[j] = dr[j];
    row[14] = 0u; row[15] = 0u;
  }
  __syncthreads();

  mlp_layer<288, 128, true>(act, wbuf, g_w + OFF_CW0, cb0, tid);   // [z, de] -> h

  // ---- tiny head (128 -> 4) + activations, fp32 scalar ----
  float* csw = reinterpret_cast<float*>(wbuf);   // cache cw1 [128][4] in smem
  csw[tid] = cw1[tid];
  csw[256 + tid] = cw1[256 + tid];
  __syncthreads();

  if (tid < 128){
    const int r = tid;
    const int g = blockIdx.x * 128 + r;
    float o0 = cb1[0], o1 = cb1[1], o2 = cb1[2], o3 = cb1[3];
    const uint32_t* row = act + r * AST;
    #pragma unroll 4
    for (int kk = 0; kk < 64; kk++){
      __half2 hu = *reinterpret_cast<const __half2*>(row + kk);
      float2 hv = __half22float2(hu);
      float4 wa = reinterpret_cast<const float4*>(csw)[2*kk];
      float4 wb = reinterpret_cast<const float4*>(csw)[2*kk + 1];
      o0 += hv.x * wa.x + hv.y * wb.x;
      o1 += hv.x * wa.y + hv.y * wb.y;
      o2 += hv.x * wa.z + hv.y * wb.z;
      o3 += hv.x * wa.w + hv.y * wb.w;
    }
    float d  = o3;
    float sp = fmaxf(d, 0.0f) + log1pf(expf(-fabsf(d)));   // stable softplus
    out[g] = (d > 8.0f) ? d : sp;
    out[nrays + g * 3 + 0] = 1.0f / (1.0f + expf(-o0));
    out[nrays + g * 3 + 1] = 1.0f / (1.0f + expf(-o1));
    out[nrays + g * 3 + 2] = 1.0f / (1.0f + expf(-o2));
  }
}

#define SMEM_BYTES ((128 * AST + 4 * 8 * WST + 128 * 14) * 4)

extern "C" void kernel_launch(void* const* d_in, const int* in_sizes, int n_in,
                              void* d_out, int out_size)
{
  const float* pos = (const float*)d_in[0];
  const float* dir = (const float*)d_in[1];
  // d_in[2..4] = pixel_width, t_start, t_end (unused by reference)
  const float* w00 = (const float*)d_in[5];  const float* b00 = (const float*)d_in[6];
  const float* w01 = (const float*)d_in[7];  const float* b01 = (const float*)d_in[8];
  const float* w02 = (const float*)d_in[9];  const float* b02 = (const float*)d_in[10];
  const float* w03 = (const float*)d_in[11]; const float* b03 = (const float*)d_in[12];
  const float* w10 = (const float*)d_in[13]; const float* b10 = (const float*)d_in[14];
  const float* w11 = (const float*)d_in[15]; const float* b11 = (const float*)d_in[16];
  const float* w12 = (const float*)d_in[17]; const float* b12 = (const float*)d_in[18];
  const float* w13 = (const float*)d_in[19]; const float* b13 = (const float*)d_in[20];
  const float* cw0 = (const float*)d_in[21]; const float* cb0 = (const float*)d_in[22];
  const float* cw1 = (const float*)d_in[23]; const float* cb1 = (const float*)d_in[24];
  float* out = (float*)d_out;

  const int nrays = in_sizes[0] / 3;

  cudaFuncSetAttribute(nerf_kernel, cudaFuncAttributeMaxDynamicSharedMemorySize, SMEM_BYTES);

  prep_all<<<(W_TOTAL + 255) / 256, 256>>>(w00, w01, w02, w03, w10, w11, w12, w13, cw0);

  nerf_kernel<<<nrays / 128, 256, SMEM_BYTES>>>(
      pos, dir, b00, b01, b02, b03, b10, b11, b12, b13, cb0, cw1, cb1, out, nrays);
}